// round 2
// baseline (speedup 1.0000x reference)
#include <cuda_runtime.h>
#include <cstdint>

// ---------------- problem constants ----------------
#define NSTK      8
#define B_ROWS    262144
#define IN_DIM    512
#define OUT_DIM   32
#define TILE_ROWS 256                    // rows per CTA
#define KSTEPS    32                     // 512 / 16
#define MAX_TILES 1032                   // sum ceil(cnt/256) <= 1024+7

// ---------------- smem layout (per CTA, dynamic) ----------------
// B fragments: [kstep 32][hilo 2][ntpair 2][thread 32][16B]  = 64 KB
// A ring     : [buf 2][hilo 2][row 256][32B]                 = 32 KB
// idx        : 256 * 4B ; bias: 32 * 4B
#define OFF_B    0
#define OFF_A    65536
#define OFF_IDX  (OFF_A + 32768)
#define OFF_BIAS (OFF_IDX + 1024)
#define SMEM_BYTES (OFF_BIAS + 128)      // 99456

// ---------------- scratch (no cudaMalloc allowed) ----------------
__device__ int g_count[NSTK];
__device__ int g_perm[NSTK * B_ROWS];

// ---------------- helpers ----------------
__device__ __forceinline__ uint32_t smem_u32(const void* p) {
    uint32_t a;
    asm("{ .reg .u64 t; cvta.to.shared.u64 t, %1; cvt.u32.u64 %0, t; }" : "=r"(a) : "l"(p));
    return a;
}
// pack two floats -> bf16x2 reg; first operand lands in HIGH half
__device__ __forceinline__ uint32_t cvt_bf16x2(float hi_elem, float lo_elem) {
    uint32_t r;
    asm("cvt.rn.bf16x2.f32 %0, %1, %2;" : "=r"(r) : "f"(hi_elem), "f"(lo_elem));
    return r;
}
__device__ __forceinline__ void sts_v2(uint32_t addr, uint32_t x, uint32_t y) {
    asm volatile("st.shared.v2.b32 [%0], {%1,%2};" :: "r"(addr), "r"(x), "r"(y) : "memory");
}
__device__ __forceinline__ void sts_b32(uint32_t addr, uint32_t x) {
    asm volatile("st.shared.b32 [%0], %1;" :: "r"(addr), "r"(x) : "memory");
}
__device__ __forceinline__ void lds_v4(uint32_t addr, uint32_t& a, uint32_t& b,
                                       uint32_t& c, uint32_t& d) {
    asm volatile("ld.shared.v4.b32 {%0,%1,%2,%3}, [%4];"
                 : "=r"(a), "=r"(b), "=r"(c), "=r"(d) : "r"(addr));
}
__device__ __forceinline__ void ldmatrix_x4(uint32_t addr, uint32_t& r0, uint32_t& r1,
                                            uint32_t& r2, uint32_t& r3) {
    asm volatile("ldmatrix.sync.aligned.m8n8.x4.shared.b16 {%0,%1,%2,%3}, [%4];"
                 : "=r"(r0), "=r"(r1), "=r"(r2), "=r"(r3) : "r"(addr));
}
__device__ __forceinline__ void mma_bf16(float& c0, float& c1, float& c2, float& c3,
                                         uint32_t a0, uint32_t a1, uint32_t a2, uint32_t a3,
                                         uint32_t b0, uint32_t b1) {
    asm volatile(
        "mma.sync.aligned.m16n8k16.row.col.f32.bf16.bf16.f32 "
        "{%0,%1,%2,%3}, {%4,%5,%6,%7}, {%8,%9}, {%0,%1,%2,%3};"
        : "+f"(c0), "+f"(c1), "+f"(c2), "+f"(c3)
        : "r"(a0), "r"(a1), "r"(a2), "r"(a3), "r"(b0), "r"(b1));
}
// split a bf16x2 hi back to the two fp32 values it represents
__device__ __forceinline__ float bf16lo_f(uint32_t h) { return __uint_as_float(h << 16); }
__device__ __forceinline__ float bf16hi_f(uint32_t h) { return __uint_as_float(h & 0xFFFF0000u); }

// ---------------- kernel 1: zero counters ----------------
__global__ void zero_counts_kernel() {
    if (threadIdx.x < NSTK) g_count[threadIdx.x] = 0;
}

// ---------------- kernel 2: bucket rows by stack ----------------
__global__ void __launch_bounds__(256) bucket_kernel(const int* __restrict__ stack_idx) {
    __shared__ int s_cnt[NSTK];
    __shared__ int s_base[NSTK];
    int tid = threadIdx.x;
    if (tid < NSTK) s_cnt[tid] = 0;
    __syncthreads();
    int r0 = blockIdx.x * 1024;
    int sv[4], lp[4];
#pragma unroll
    for (int j = 0; j < 4; j++) {
        int row = r0 + tid + j * 256;
        int s = stack_idx[row];
        sv[j] = s;
        lp[j] = atomicAdd(&s_cnt[s], 1);
    }
    __syncthreads();
    if (tid < NSTK) s_base[tid] = atomicAdd(&g_count[tid], s_cnt[tid]);
    __syncthreads();
#pragma unroll
    for (int j = 0; j < 4; j++) {
        int row = r0 + tid + j * 256;
        g_perm[sv[j] * B_ROWS + s_base[sv[j]] + lp[j]] = row;
    }
}

// ---------------- kernel 3: gathered split-bf16 mma.sync GEMM ----------------
__global__ void __launch_bounds__(256, 2) gemm_kernel(
    const float* __restrict__ input, const float* __restrict__ weight,
    const float* __restrict__ bias, float* __restrict__ out)
{
    // map block -> (stack, tile) via prefix over ceil(count/256)
    int cnt[NSTK];
#pragma unroll
    for (int i = 0; i < NSTK; i++) cnt[i] = g_count[i];
    int s = -1, t = 0, acc0 = 0;
#pragma unroll
    for (int i = 0; i < NSTK; i++) {
        int ts = (cnt[i] + TILE_ROWS - 1) >> 8;
        if (s < 0 && (int)blockIdx.x < acc0 + ts) { s = i; t = blockIdx.x - acc0; }
        acc0 += ts;
    }
    if (s < 0) return;
    int count = cnt[s];

    extern __shared__ char smem[];
    uint32_t sb = smem_u32(smem);
    int tid = threadIdx.x;
    int wid = tid >> 5, lane = tid & 31;

    // row indices + bias into smem
    {
        int p = t * TILE_ROWS + tid;
        ((int*)(smem + OFF_IDX))[tid] = (p < count) ? g_perm[s * B_ROWS + p] : -1;
        if (tid < OUT_DIM)
            ((float*)(smem + OFF_BIAS))[tid] = bias[s * OUT_DIM + tid];
    }

    // ---- stage B (weight) into fragment-ordered hi/lo smem ----
    // layout byte: ks*2048 + hilo*1024 + ntpair*512 + thr*16 + sub*8 + ((kk>>3)&1)*4
    {
        const float4* wv = (const float4*)(weight + (size_t)s * OUT_DIM * IN_DIM);
#pragma unroll
        for (int j = 0; j < (OUT_DIM * IN_DIM / 4) / TILE_ROWS; j++) {   // 16 iters
            int v = tid + TILE_ROWS * j;      // v = o*128 + f4
            int o = v >> 7, f4 = v & 127;
            int k0 = f4 * 4;
            float4 w = wv[v];
            uint32_t h01 = cvt_bf16x2(w.y, w.x);
            uint32_t h23 = cvt_bf16x2(w.w, w.z);
            uint32_t l01 = cvt_bf16x2(w.y - bf16hi_f(h01), w.x - bf16lo_f(h01));
            uint32_t l23 = cvt_bf16x2(w.w - bf16hi_f(h23), w.z - bf16lo_f(h23));
            int ks = k0 >> 4, kk = k0 & 15;
            int t0 = ((o & 7) << 2) + ((kk & 4) >> 1);
            int ntile = o >> 3;
            uint32_t base = sb + OFF_B + (uint32_t)ks * 2048u + ((ntile >> 1) * 512u)
                          + ((ntile & 1) * 8u) + (((kk >> 3) & 1) * 4u);
            sts_b32(base + t0 * 16, h01);
            sts_b32(base + (t0 + 1) * 16, h23);
            sts_b32(base + 1024 + t0 * 16, l01);
            sts_b32(base + 1024 + (t0 + 1) * 16, l23);
        }
    }
    __syncthreads();

    // ---- per-thread gather setup: thread owns block-row `tid` ----
    int g = ((int*)(smem + OFF_IDX))[tid];
    if (g < 0) g = 0;
    const float4* xv = (const float4*)input + (size_t)g * (IN_DIM / 4);

    // ldmatrix read offsets (per mtile), relative to A plane base
    uint32_t a_off[2];
#pragma unroll
    for (int m = 0; m < 2; m++) {
        int rowm = wid * 32 + m * 16 + (lane & 15);
        a_off[m] = (uint32_t)rowm * 32u + ((((lane >> 4) ^ ((rowm >> 2) & 1)) & 1) << 4);
    }
    uint32_t b_off = sb + OFF_B + lane * 16;     // + ks*2048 + p*512 (+1024 lo)
    int rrot = (tid >> 2) & 3;                   // STS q-rotation
    int rsw  = (tid >> 2) & 1;                   // 16B swizzle bit

    float acc[2][4][4];
#pragma unroll
    for (int m = 0; m < 2; m++)
#pragma unroll
        for (int n = 0; n < 4; n++)
#pragma unroll
            for (int e = 0; e < 4; e++) acc[m][n][e] = 0.0f;

    // prefetch kstep 0
    float4 ra[4];
#pragma unroll
    for (int q = 0; q < 4; q++) ra[q] = xv[q];

    for (int c = 0; c < KSTEPS; c++) {
        uint32_t ab = sb + OFF_A + (uint32_t)(c & 1) * 16384u;

        // --- scatter A (hi/lo split) into smem, conflict-free rotated order ---
#pragma unroll
        for (int i = 0; i < 4; i++) {
            int q = (i + rrot) & 3;
            float4 v = ra[q];
            uint32_t h01 = cvt_bf16x2(v.y, v.x);
            uint32_t h23 = cvt_bf16x2(v.w, v.z);
            uint32_t l01 = cvt_bf16x2(v.y - bf16hi_f(h01), v.x - bf16lo_f(h01));
            uint32_t l23 = cvt_bf16x2(v.w - bf16hi_f(h23), v.z - bf16lo_f(h23));
            uint32_t off = (uint32_t)tid * 32u + (uint32_t)((((q >> 1) ^ rsw) & 1) << 4)
                         + (uint32_t)((q & 1) << 3);
            sts_v2(ab + off, h01, h23);
            sts_v2(ab + 8192 + off, l01, l23);
        }
        // prefetch next kstep
        if (c + 1 < KSTEPS) {
#pragma unroll
            for (int q = 0; q < 4; q++) ra[q] = xv[(c + 1) * 4 + q];
        }
        __syncthreads();

        // --- consume: ldmatrix A hi/lo, LDS B hi/lo, 24 MMAs ---
        uint32_t Ah[2][4], Al[2][4];
#pragma unroll
        for (int m = 0; m < 2; m++) {
            ldmatrix_x4(ab + a_off[m],        Ah[m][0], Ah[m][1], Ah[m][2], Ah[m][3]);
            ldmatrix_x4(ab + 8192 + a_off[m], Al[m][0], Al[m][1], Al[m][2], Al[m][3]);
        }
        uint32_t Bh[2][4], Bl[2][4];
        uint32_t bks = b_off + (uint32_t)c * 2048u;
#pragma unroll
        for (int p = 0; p < 2; p++) {
            lds_v4(bks + p * 512u,         Bh[p][0], Bh[p][1], Bh[p][2], Bh[p][3]);
            lds_v4(bks + 1024u + p * 512u, Bl[p][0], Bl[p][1], Bl[p][2], Bl[p][3]);
        }
#pragma unroll
        for (int m = 0; m < 2; m++) {
#pragma unroll
            for (int n = 0; n < 4; n++) {
                int p = n >> 1, sub = (n & 1) * 2;
                uint32_t bh0 = Bh[p][sub], bh1 = Bh[p][sub + 1];
                uint32_t bl0 = Bl[p][sub], bl1 = Bl[p][sub + 1];
                mma_bf16(acc[m][n][0], acc[m][n][1], acc[m][n][2], acc[m][n][3],
                         Ah[m][0], Ah[m][1], Ah[m][2], Ah[m][3], bh0, bh1);
                mma_bf16(acc[m][n][0], acc[m][n][1], acc[m][n][2], acc[m][n][3],
                         Ah[m][0], Ah[m][1], Ah[m][2], Ah[m][3], bl0, bl1);
                mma_bf16(acc[m][n][0], acc[m][n][1], acc[m][n][2], acc[m][n][3],
                         Al[m][0], Al[m][1], Al[m][2], Al[m][3], bh0, bh1);
            }
        }
        __syncthreads();
    }

    // ---- epilogue: add bias, scatter rows to gmem ----
    const float* bsp = (const float*)(smem + OFF_BIAS);
    const int* idxp = (const int*)(smem + OFF_IDX);
    int c2 = (lane & 3) * 2;
    float2 bv[4];
#pragma unroll
    for (int n = 0; n < 4; n++) {
        bv[n].x = bsp[n * 8 + c2];
        bv[n].y = bsp[n * 8 + c2 + 1];
    }
#pragma unroll
    for (int m = 0; m < 2; m++) {
#pragma unroll
        for (int hf = 0; hf < 2; hf++) {
            int rr = wid * 32 + m * 16 + (lane >> 2) + hf * 8;
            int go = idxp[rr];
            if (go >= 0) {
                float* op = out + (size_t)go * OUT_DIM;
#pragma unroll
                for (int n = 0; n < 4; n++) {
                    float2 v;
                    v.x = acc[m][n][hf * 2]     + bv[n].x;
                    v.y = acc[m][n][hf * 2 + 1] + bv[n].y;
                    *(float2*)(op + n * 8 + c2) = v;
                }
            }
        }
    }
}

// ---------------- launcher ----------------
extern "C" void kernel_launch(void* const* d_in, const int* in_sizes, int n_in,
                              void* d_out, int out_size) {
    const float* input  = (const float*)d_in[0];
    const int*   sidx   = (const int*)d_in[1];
    const float* weight = (const float*)d_in[2];
    const float* bias   = (const float*)d_in[3];
    float* out = (float*)d_out;

    zero_counts_kernel<<<1, 32>>>();
    bucket_kernel<<<B_ROWS / 1024, 256>>>(sidx);

    cudaFuncSetAttribute(gemm_kernel, cudaFuncAttributeMaxDynamicSharedMemorySize, SMEM_BYTES);
    gemm_kernel<<<MAX_TILES, 256, SMEM_BYTES>>>(input, weight, bias, out);
}

// round 3
// speedup vs baseline: 1.0023x; 1.0023x over previous
#include <cuda_runtime.h>
#include <cstdint>

// ---------------- problem constants ----------------
#define NSTK      8
#define B_ROWS    262144
#define IN_DIM    512
#define OUT_DIM   32
#define TILE_ROWS 256                    // rows per CTA
#define KSTEPS    32                     // 512 / 16
#define MAX_TILES 1032                   // sum ceil(cnt/256) <= 1024+7

// ---------------- smem layout (per CTA, dynamic) ----------------
// B fragments: [kstep 32][hilo 2][ntpair 2][thread 32][16B]  = 64 KB
// A ring     : [buf 2][hilo 2][row 256][32B]                 = 32 KB
// idx        : 256 * 4B ; bias: 32 * 4B
#define OFF_B    0
#define OFF_A    65536
#define OFF_IDX  (OFF_A + 32768)
#define OFF_BIAS (OFF_IDX + 1024)
#define SMEM_BYTES (OFF_BIAS + 128)      // 99456

// ---------------- scratch (no cudaMalloc allowed) ----------------
__device__ int g_count[NSTK];
__device__ int g_perm[NSTK * B_ROWS];

// ---------------- helpers ----------------
__device__ __forceinline__ uint32_t smem_u32(const void* p) {
    uint32_t a;
    asm("{ .reg .u64 t; cvta.to.shared.u64 t, %1; cvt.u32.u64 %0, t; }" : "=r"(a) : "l"(p));
    return a;
}
// pack two floats -> bf16x2 reg; first operand lands in HIGH half
__device__ __forceinline__ uint32_t cvt_bf16x2(float hi_elem, float lo_elem) {
    uint32_t r;
    asm("cvt.rn.bf16x2.f32 %0, %1, %2;" : "=r"(r) : "f"(hi_elem), "f"(lo_elem));
    return r;
}
__device__ __forceinline__ void sts_v2(uint32_t addr, uint32_t x, uint32_t y) {
    asm volatile("st.shared.v2.b32 [%0], {%1,%2};" :: "r"(addr), "r"(x), "r"(y) : "memory");
}
__device__ __forceinline__ void sts_b32(uint32_t addr, uint32_t x) {
    asm volatile("st.shared.b32 [%0], %1;" :: "r"(addr), "r"(x) : "memory");
}
__device__ __forceinline__ void lds_v4(uint32_t addr, uint32_t& a, uint32_t& b,
                                       uint32_t& c, uint32_t& d) {
    asm volatile("ld.shared.v4.b32 {%0,%1,%2,%3}, [%4];"
                 : "=r"(a), "=r"(b), "=r"(c), "=r"(d) : "r"(addr));
}
__device__ __forceinline__ void ldmatrix_x4(uint32_t addr, uint32_t& r0, uint32_t& r1,
                                            uint32_t& r2, uint32_t& r3) {
    asm volatile("ldmatrix.sync.aligned.m8n8.x4.shared.b16 {%0,%1,%2,%3}, [%4];"
                 : "=r"(r0), "=r"(r1), "=r"(r2), "=r"(r3) : "r"(addr));
}
__device__ __forceinline__ void mma_bf16(float& c0, float& c1, float& c2, float& c3,
                                         uint32_t a0, uint32_t a1, uint32_t a2, uint32_t a3,
                                         uint32_t b0, uint32_t b1) {
    asm volatile(
        "mma.sync.aligned.m16n8k16.row.col.f32.bf16.bf16.f32 "
        "{%0,%1,%2,%3}, {%4,%5,%6,%7}, {%8,%9}, {%0,%1,%2,%3};"
        : "+f"(c0), "+f"(c1), "+f"(c2), "+f"(c3)
        : "r"(a0), "r"(a1), "r"(a2), "r"(a3), "r"(b0), "r"(b1));
}
// split a bf16x2 hi back to the two fp32 values it represents
__device__ __forceinline__ float bf16lo_f(uint32_t h) { return __uint_as_float(h << 16); }
__device__ __forceinline__ float bf16hi_f(uint32_t h) { return __uint_as_float(h & 0xFFFF0000u); }

// ---------------- kernel 1: zero counters ----------------
__global__ void zero_counts_kernel() {
    if (threadIdx.x < NSTK) g_count[threadIdx.x] = 0;
}

// ---------------- kernel 2: bucket rows by stack ----------------
__global__ void __launch_bounds__(256) bucket_kernel(const int* __restrict__ stack_idx) {
    __shared__ int s_cnt[NSTK];
    __shared__ int s_base[NSTK];
    int tid = threadIdx.x;
    if (tid < NSTK) s_cnt[tid] = 0;
    __syncthreads();
    int r0 = blockIdx.x * 1024;
    int sv[4], lp[4];
#pragma unroll
    for (int j = 0; j < 4; j++) {
        int row = r0 + tid + j * 256;
        int s = stack_idx[row];
        sv[j] = s;
        lp[j] = atomicAdd(&s_cnt[s], 1);
    }
    __syncthreads();
    if (tid < NSTK) s_base[tid] = atomicAdd(&g_count[tid], s_cnt[tid]);
    __syncthreads();
#pragma unroll
    for (int j = 0; j < 4; j++) {
        int row = r0 + tid + j * 256;
        g_perm[sv[j] * B_ROWS + s_base[sv[j]] + lp[j]] = row;
    }
}

// ---------------- kernel 3: gathered split-bf16 mma.sync GEMM ----------------
__global__ void __launch_bounds__(256, 2) gemm_kernel(
    const float* __restrict__ input, const float* __restrict__ weight,
    const float* __restrict__ bias, float* __restrict__ out)
{
    // map block -> (stack, tile) via prefix over ceil(count/256)
    int cnt[NSTK];
#pragma unroll
    for (int i = 0; i < NSTK; i++) cnt[i] = g_count[i];
    int s = -1, t = 0, acc0 = 0;
#pragma unroll
    for (int i = 0; i < NSTK; i++) {
        int ts = (cnt[i] + TILE_ROWS - 1) >> 8;
        if (s < 0 && (int)blockIdx.x < acc0 + ts) { s = i; t = blockIdx.x - acc0; }
        acc0 += ts;
    }
    if (s < 0) return;
    int count = cnt[s];

    extern __shared__ char smem[];
    uint32_t sb = smem_u32(smem);
    int tid = threadIdx.x;
    int wid = tid >> 5, lane = tid & 31;

    // row indices + bias into smem
    {
        int p = t * TILE_ROWS + tid;
        ((int*)(smem + OFF_IDX))[tid] = (p < count) ? g_perm[s * B_ROWS + p] : -1;
        if (tid < OUT_DIM)
            ((float*)(smem + OFF_BIAS))[tid] = bias[s * OUT_DIM + tid];
    }

    // ---- stage B (weight) into fragment-ordered hi/lo smem ----
    // layout byte: ks*2048 + hilo*1024 + ntpair*512 + thr*16 + sub*8 + ((kk>>3)&1)*4
    {
        const float4* wv = (const float4*)(weight + (size_t)s * OUT_DIM * IN_DIM);
#pragma unroll
        for (int j = 0; j < (OUT_DIM * IN_DIM / 4) / TILE_ROWS; j++) {   // 16 iters
            int v = tid + TILE_ROWS * j;      // v = o*128 + f4
            int o = v >> 7, f4 = v & 127;
            int k0 = f4 * 4;
            float4 w = wv[v];
            uint32_t h01 = cvt_bf16x2(w.y, w.x);
            uint32_t h23 = cvt_bf16x2(w.w, w.z);
            uint32_t l01 = cvt_bf16x2(w.y - bf16hi_f(h01), w.x - bf16lo_f(h01));
            uint32_t l23 = cvt_bf16x2(w.w - bf16hi_f(h23), w.z - bf16lo_f(h23));
            int ks = k0 >> 4, kk = k0 & 15;
            int t0 = ((o & 7) << 2) + ((kk & 4) >> 1);
            int ntile = o >> 3;
            uint32_t base = sb + OFF_B + (uint32_t)ks * 2048u + ((ntile >> 1) * 512u)
                          + ((ntile & 1) * 8u) + (((kk >> 3) & 1) * 4u);
            sts_b32(base + t0 * 16, h01);
            sts_b32(base + (t0 + 1) * 16, h23);
            sts_b32(base + 1024 + t0 * 16, l01);
            sts_b32(base + 1024 + (t0 + 1) * 16, l23);
        }
    }
    __syncthreads();

    // ---- per-thread gather setup: thread owns block-row `tid` ----
    int g = ((int*)(smem + OFF_IDX))[tid];
    if (g < 0) g = 0;
    const float4* xv = (const float4*)input + (size_t)g * (IN_DIM / 4);

    // ldmatrix read offsets (per mtile), relative to A plane base
    uint32_t a_off[2];
#pragma unroll
    for (int m = 0; m < 2; m++) {
        int rowm = wid * 32 + m * 16 + (lane & 15);
        a_off[m] = (uint32_t)rowm * 32u + ((((lane >> 4) ^ ((rowm >> 2) & 1)) & 1) << 4);
    }
    uint32_t b_off = sb + OFF_B + lane * 16;     // + ks*2048 + p*512 (+1024 lo)
    int rrot = (tid >> 2) & 3;                   // STS q-rotation
    int rsw  = (tid >> 2) & 1;                   // 16B swizzle bit

    float acc[2][4][4];
#pragma unroll
    for (int m = 0; m < 2; m++)
#pragma unroll
        for (int n = 0; n < 4; n++)
#pragma unroll
            for (int e = 0; e < 4; e++) acc[m][n][e] = 0.0f;

    // prefetch kstep 0
    float4 ra[4];
#pragma unroll
    for (int q = 0; q < 4; q++) ra[q] = xv[q];

    for (int c = 0; c < KSTEPS; c++) {
        uint32_t ab = sb + OFF_A + (uint32_t)(c & 1) * 16384u;

        // --- scatter A (hi/lo split) into smem, conflict-free rotated order ---
#pragma unroll
        for (int i = 0; i < 4; i++) {
            int q = (i + rrot) & 3;
            float4 v = ra[q];
            uint32_t h01 = cvt_bf16x2(v.y, v.x);
            uint32_t h23 = cvt_bf16x2(v.w, v.z);
            uint32_t l01 = cvt_bf16x2(v.y - bf16hi_f(h01), v.x - bf16lo_f(h01));
            uint32_t l23 = cvt_bf16x2(v.w - bf16hi_f(h23), v.z - bf16lo_f(h23));
            uint32_t off = (uint32_t)tid * 32u + (uint32_t)((((q >> 1) ^ rsw) & 1) << 4)
                         + (uint32_t)((q & 1) << 3);
            sts_v2(ab + off, h01, h23);
            sts_v2(ab + 8192 + off, l01, l23);
        }
        // prefetch next kstep
        if (c + 1 < KSTEPS) {
#pragma unroll
            for (int q = 0; q < 4; q++) ra[q] = xv[(c + 1) * 4 + q];
        }
        __syncthreads();

        // --- consume: ldmatrix A hi/lo, LDS B hi/lo, 24 MMAs ---
        uint32_t Ah[2][4], Al[2][4];
#pragma unroll
        for (int m = 0; m < 2; m++) {
            ldmatrix_x4(ab + a_off[m],        Ah[m][0], Ah[m][1], Ah[m][2], Ah[m][3]);
            ldmatrix_x4(ab + 8192 + a_off[m], Al[m][0], Al[m][1], Al[m][2], Al[m][3]);
        }
        uint32_t Bh[2][4], Bl[2][4];
        uint32_t bks = b_off + (uint32_t)c * 2048u;
#pragma unroll
        for (int p = 0; p < 2; p++) {
            lds_v4(bks + p * 512u,         Bh[p][0], Bh[p][1], Bh[p][2], Bh[p][3]);
            lds_v4(bks + 1024u + p * 512u, Bl[p][0], Bl[p][1], Bl[p][2], Bl[p][3]);
        }
#pragma unroll
        for (int m = 0; m < 2; m++) {
#pragma unroll
            for (int n = 0; n < 4; n++) {
                int p = n >> 1, sub = (n & 1) * 2;
                uint32_t bh0 = Bh[p][sub], bh1 = Bh[p][sub + 1];
                uint32_t bl0 = Bl[p][sub], bl1 = Bl[p][sub + 1];
                mma_bf16(acc[m][n][0], acc[m][n][1], acc[m][n][2], acc[m][n][3],
                         Ah[m][0], Ah[m][1], Ah[m][2], Ah[m][3], bh0, bh1);
                mma_bf16(acc[m][n][0], acc[m][n][1], acc[m][n][2], acc[m][n][3],
                         Ah[m][0], Ah[m][1], Ah[m][2], Ah[m][3], bl0, bl1);
                mma_bf16(acc[m][n][0], acc[m][n][1], acc[m][n][2], acc[m][n][3],
                         Al[m][0], Al[m][1], Al[m][2], Al[m][3], bh0, bh1);
            }
        }
        __syncthreads();
    }

    // ---- epilogue: add bias, scatter rows to gmem ----
    const float* bsp = (const float*)(smem + OFF_BIAS);
    const int* idxp = (const int*)(smem + OFF_IDX);
    int c2 = (lane & 3) * 2;
    float2 bv[4];
#pragma unroll
    for (int n = 0; n < 4; n++) {
        bv[n].x = bsp[n * 8 + c2];
        bv[n].y = bsp[n * 8 + c2 + 1];
    }
#pragma unroll
    for (int m = 0; m < 2; m++) {
#pragma unroll
        for (int hf = 0; hf < 2; hf++) {
            int rr = wid * 32 + m * 16 + (lane >> 2) + hf * 8;
            int go = idxp[rr];
            if (go >= 0) {
                float* op = out + (size_t)go * OUT_DIM;
#pragma unroll
                for (int n = 0; n < 4; n++) {
                    float2 v;
                    v.x = acc[m][n][hf * 2]     + bv[n].x;
                    v.y = acc[m][n][hf * 2 + 1] + bv[n].y;
                    *(float2*)(op + n * 8 + c2) = v;
                }
            }
        }
    }
}

// ---------------- launcher ----------------
extern "C" void kernel_launch(void* const* d_in, const int* in_sizes, int n_in,
                              void* d_out, int out_size) {
    const float* input  = (const float*)d_in[0];
    const int*   sidx   = (const int*)d_in[1];
    const float* weight = (const float*)d_in[2];
    const float* bias   = (const float*)d_in[3];
    float* out = (float*)d_out;

    zero_counts_kernel<<<1, 32>>>();
    bucket_kernel<<<B_ROWS / 1024, 256>>>(sidx);

    cudaFuncSetAttribute(gemm_kernel, cudaFuncAttributeMaxDynamicSharedMemorySize, SMEM_BYTES);
    gemm_kernel<<<MAX_TILES, 256, SMEM_BYTES>>>(input, weight, bias, out);
}